// round 7
// baseline (speedup 1.0000x reference)
#include <cuda_runtime.h>
#include <cstdint>

// ============================================================================
// BESNumEigen3qubitModel — analytic restructuring + packed f32x2 Jacobi.
// 3 Hermitian 8x8 eigenproblems per batch element (rho, pt_a, pt_c);
// dm0/dm1 eigenvalues are affine maps beta*(w - 1/8) + 1/8 of rho's.
//
// R7: fixed-5 unconditional sweeps + up to 3 guarded extra sweeps (checks
// only when they can matter); 64-thread blocks for finer occupancy
// granularity (cap 128 regs, same as before worst-case).
// ============================================================================

#define BMAX 32768

__device__ float g_eigs[3 * BMAX * 8];

using u64 = unsigned long long;

// ---------------------------------------------------------------------------
// packed f32x2 helpers
// ---------------------------------------------------------------------------
__device__ __forceinline__ u64 pk2(float lo, float hi) {
    u64 r; asm("mov.b64 %0, {%1, %2};" : "=l"(r) : "f"(lo), "f"(hi)); return r;
}
__device__ __forceinline__ void upk2(u64 v, float& lo, float& hi) {
    asm("mov.b64 {%0, %1}, %2;" : "=f"(lo), "=f"(hi) : "l"(v));
}
__device__ __forceinline__ u64 f2fma(u64 a, u64 b, u64 c) {
    u64 r; asm("fma.rn.f32x2 %0, %1, %2, %3;" : "=l"(r) : "l"(a), "l"(b), "l"(c));
    return r;
}
__device__ __forceinline__ u64 f2mul(u64 a, u64 b) {
    u64 r; asm("mul.rn.f32x2 %0, %1, %2;" : "=l"(r) : "l"(a), "l"(b));
    return r;
}
__device__ __forceinline__ u64 sw2(u64 v) {      // (lo,hi) -> (hi,lo)
    float lo, hi; upk2(v, lo, hi); return pk2(hi, lo);
}
__device__ __forceinline__ u64 cj2(u64 v) {      // conj: negate imag (hi) lane
    return v ^ 0x8000000000000000ULL;
}

// upper-triangle linear index for j<k
__host__ __device__ constexpr int uidx(int j, int k) {
    return 7 * j - (j * (j - 1)) / 2 + (k - j - 1);
}

// ---------------------------------------------------------------------------
// partial-transpose index permutations (applied at build time)
// pt_a swaps the 'a' bit (4), pt_c swaps the 'c' bit (1). Diagonal fixed.
// ---------------------------------------------------------------------------
__host__ __device__ constexpr int permR(int TYPE, int j, int k) {
    return TYPE == 0 ? j : (TYPE == 1 ? ((j & 3) | (k & 4)) : ((j & 6) | (k & 1)));
}
__host__ __device__ constexpr int permC(int TYPE, int j, int k) {
    return TYPE == 0 ? k : (TYPE == 1 ? ((k & 3) | (j & 4)) : ((k & 6) | (j & 1)));
}

// ---------------------------------------------------------------------------
// Build packed upper triangle m[28] + real diagonal d[8] of the (possibly
// partially transposed) normalized density matrix.
// v layout: [0..27] symmetric pairs, [28..55] antisymmetric, [56..62] diag.
// ---------------------------------------------------------------------------
template <int TYPE>
__device__ __forceinline__ void build8(const float* __restrict__ v,
                                       u64 m[28], float d[8]) {
    const float COEF[7] = {
        1.0f, 0.5773502691896258f, 0.4082482904638631f, 0.31622776601683794f,
        0.2581988897471611f, 0.21821789023599236f, 0.1889822365046136f
    };

    float ss = 0.f;
    float dd[8];
#pragma unroll
    for (int j = 0; j < 8; ++j) dd[j] = 0.f;

#pragma unroll
    for (int l = 1; l <= 7; ++l) {
        float x = v[55 + l];
        ss += x * x;
        x *= COEF[l - 1];
#pragma unroll
        for (int j = 0; j < 7; ++j)
            if (j < l) dd[j] += x;
        dd[l] -= (float)l * x;
    }

#pragma unroll
    for (int j = 0; j < 8; ++j) {
#pragma unroll
        for (int k = j + 1; k < 8; ++k) {
            const int p = uidx(j, k);
            float vs = v[p];
            float va = v[28 + p];
            ss += vs * vs + va * va;
            // element at permuted (R,C) is vs - i*va; mirror is conjugate
            const int R = permR(TYPE, j, k), C = permC(TYPE, j, k);
            if (R < C) m[uidx(R, C)] = pk2(vs, -va);
            else       m[uidx(C, R)] = pk2(vs,  va);
        }
    }

    float inv = rsqrtf(ss);
    u64 inv2 = pk2(inv, inv);
#pragma unroll
    for (int i = 0; i < 28; ++i) m[i] = f2mul(m[i], inv2);
#pragma unroll
    for (int j = 0; j < 8; ++j) d[j] = 0.125f + dd[j] * inv;
}

// ---------------------------------------------------------------------------
// One round-robin Jacobi sweep: 7 rounds x 4 disjoint pivot pairs.
// Angles per round computed up-front (ILP-4 MUFU chains), then 4 commuting
// rotation updates applied.
// ---------------------------------------------------------------------------
__device__ __forceinline__ void jacobi_sweep(u64 m[28], float d[8]) {
    constexpr int SCHED[7][4][2] = {
        {{0,1},{2,7},{3,6},{4,5}},
        {{0,2},{1,3},{4,7},{5,6}},
        {{0,3},{2,4},{1,5},{6,7}},
        {{0,4},{3,5},{2,6},{1,7}},
        {{0,5},{4,6},{3,7},{1,2}},
        {{0,6},{5,7},{1,4},{2,3}},
        {{0,7},{1,6},{2,5},{3,4}}
    };

#pragma unroll
    for (int r = 0; r < 7; ++r) {
        // ---- phase 1: 4 independent angle computations (ILP-4) ----
        float C[4], SR[4], SI[4];
#pragma unroll
        for (int i = 0; i < 4; ++i) {
            const int p = SCHED[r][i][0], q = SCHED[r][i][1];
            float xr, xi; upk2(m[uidx(p, q)], xr, xi);
            float r2 = xr * xr + xi * xi;
            float h = (d[q] - d[p]) * 0.5f;
            float hyp = sqrtf(h * h + r2);
            float den = h + copysignf(hyp, h);
            float inv = rsqrtf(fmaxf(den * den + r2, 1e-38f));
            float inv_s = copysignf(inv, den);
            float c   = den * inv_s;          // = |den|*inv >= 0
            float scr = xr * inv_s;           // Re(s*u)
            float sci = xi * inv_s;           // Im(s*u)
            float tr  = __fdividef(r2, den);  // t*|a_pq|
            bool doit = r2 > 1e-28f;
            c   = doit ? c   : 1.f;
            scr = doit ? scr : 0.f;
            sci = doit ? sci : 0.f;
            tr  = doit ? tr  : 0.f;

            d[p] -= tr;
            d[q] += tr;
            m[uidx(p, q)] = 0ULL;
            C[i] = c; SR[i] = scr; SI[i] = sci;
        }

        // ---- phase 2: apply the 4 (commuting) rotation updates ----
#pragma unroll
        for (int i = 0; i < 4; ++i) {
            const int p = SCHED[r][i][0], q = SCHED[r][i][1];
            const float c = C[i], scr = SR[i], sci = SI[i];
            const u64 c2    = pk2(c, c);
            const u64 scr2  = pk2(scr, scr);
            const u64 mscr2 = pk2(-scr, -scr);
            const u64 spm   = pk2(-sci,  sci);   // actual-coord updates
            const u64 spc   = pk2( sci, -sci);   // conj-stored updates

            // k != p,q:
            //   np = c*kp - conj(su)*kq = c2.kp + mscr2.kq + spm.sw(kq)
            //   nq = su*kp + c*kq       = scr2.kp + spm.sw(kp) + c2.kq
            // k>q: both conj-stored -> same recurrence with spm -> spc.
            // p<k<q: p-side conj-stored -> fix with 2 XORs.
#pragma unroll
            for (int k = 0; k < 8; ++k) {
                if (k == p || k == q) continue;
                if (k < p) {
                    u64 zp = m[uidx(k, p)], zq = m[uidx(k, q)];
                    u64 np = f2fma(spm, sw2(zq), f2fma(mscr2, zq, f2mul(c2, zp)));
                    u64 nq = f2fma(spm, sw2(zp), f2fma(scr2,  zp, f2mul(c2, zq)));
                    m[uidx(k, p)] = np; m[uidx(k, q)] = nq;
                } else if (k > q) {
                    u64 zp = m[uidx(p, k)], zq = m[uidx(q, k)];
                    u64 np = f2fma(spc, sw2(zq), f2fma(mscr2, zq, f2mul(c2, zp)));
                    u64 nq = f2fma(spc, sw2(zp), f2fma(scr2,  zp, f2mul(c2, zq)));
                    m[uidx(p, k)] = np; m[uidx(q, k)] = nq;
                } else {   // p < k < q
                    u64 zp = cj2(m[uidx(p, k)]), zq = m[uidx(k, q)];
                    u64 np = f2fma(spm, sw2(zq), f2fma(mscr2, zq, f2mul(c2, zp)));
                    u64 nq = f2fma(spm, sw2(zp), f2fma(scr2,  zp, f2mul(c2, zq)));
                    m[uidx(p, k)] = cj2(np); m[uidx(k, q)] = nq;
                }
            }
        }
    }
}

// ---------------------------------------------------------------------------
// Jacobi driver: 5 unconditional sweeps, then up to 3 more gated by the
// off-diagonal norm check (warp-uniform exit). Single sweep body in binary.
// ---------------------------------------------------------------------------
__device__ __forceinline__ void jacobi8h(u64 m[28], float d[8]) {
#pragma unroll 1
    for (int sweep = 0; sweep < 8; ++sweep) {
        if (sweep >= 5) {
            u64 acc = 0ULL;
#pragma unroll
            for (int i = 0; i < 28; ++i) acc = f2fma(m[i], m[i], acc);
            float o1, o2; upk2(acc, o1, o2);
            if (__all_sync(0xFFFFFFFFu, o1 + o2 < 1e-10f)) break;
        }
        jacobi_sweep(m, d);
    }
}

// ---------------------------------------------------------------------------
// 8-element sorting network (19 comparators, ascending)
// ---------------------------------------------------------------------------
__device__ __forceinline__ void sort8(float w[8]) {
#define CAS(i, j) { float lo = fminf(w[i], w[j]); float hi = fmaxf(w[i], w[j]); w[i] = lo; w[j] = hi; }
    CAS(0,1) CAS(2,3) CAS(4,5) CAS(6,7)
    CAS(0,2) CAS(1,3) CAS(4,6) CAS(5,7)
    CAS(1,2) CAS(5,6) CAS(0,4) CAS(3,7)
    CAS(1,5) CAS(2,6)
    CAS(1,4) CAS(3,6)
    CAS(2,4) CAS(3,5)
    CAS(3,4)
#undef CAS
}

// ---------------------------------------------------------------------------
// Kernel 1: one thread per (type, batch). gridDim.y = type. 64-thread blocks
// for finer occupancy granularity; smem-staged coalesced input loads
// (LDS stride 63 words is coprime with 32 banks -> conflict-free).
// ---------------------------------------------------------------------------
__global__ void __launch_bounds__(64, 8)
eig_kernel(const float* __restrict__ rho_vec, int n) {
    __shared__ float sv[64 * 63];

    const int base = blockIdx.x * 64;
    const int rows = min(64, n - base);
    const int total = rows * 63;
    const float* src = rho_vec + (size_t)base * 63;
    for (int i = threadIdx.x; i < total; i += 64) sv[i] = src[i];
    __syncthreads();

    int b = base + threadIdx.x;
    const bool valid = (b < n);
    const int row = valid ? threadIdx.x : 0;   // clamp for __all_sync safety
    const int type = blockIdx.y;

    const float* v = sv + row * 63;

    u64 m[28];
    float d[8];
    if (type == 0)      build8<0>(v, m, d);
    else if (type == 1) build8<1>(v, m, d);
    else                build8<2>(v, m, d);

    jacobi8h(m, d);
    sort8(d);

    if (valid) {
        float4* dst = reinterpret_cast<float4*>(g_eigs + ((size_t)type * n + b) * 8);
        dst[0] = make_float4(d[0], d[1], d[2], d[3]);
        dst[1] = make_float4(d[4], d[5], d[6], d[7]);
    }
}

// ---------------------------------------------------------------------------
// Kernel 2: combine per-matrix eigenvalue summaries into the loss.
// ---------------------------------------------------------------------------
__global__ void __launch_bounds__(256)
combine_kernel(const int* __restrict__ rank0p, const int* __restrict__ rank1p,
               float* __restrict__ out, int n) {
    int b = blockIdx.x * blockDim.x + threadIdx.x;
    if (b >= n) return;

    const float* w  = g_eigs + (size_t)b * 8;
    const float* ea = g_eigs + ((size_t)n + b) * 8;
    const float* ec = g_eigs + ((size_t)2 * n + b) * 8;

    float wv[8];
#pragma unroll
    for (int i = 0; i < 8; ++i) wv[i] = w[i];

    const float beta0 = 1.f / (1.f - 8.f * wv[0]);
    const float beta1 = 1.f / (1.f - 8.f * wv[7]);

    const int n0 = 8 - *rank0p;
    const int n1 = 8 - *rank1p;

    float S0 = 0.f, S1 = 0.f;
#pragma unroll
    for (int i = 0; i < 8; ++i) {
        if (i < n0)       S0 += wv[i];        // n0 smallest of w
        if (i >= 8 - n1)  S1 += wv[i];        // n1 largest  of w
    }

    const float loss0 = beta0 * (S0 - 0.125f * (float)n0) + 0.125f * (float)n0;
    const float loss1 = beta1 * (S1 - 0.125f * (float)n1) + 0.125f * (float)n1;
    const float tsum = loss0 + loss1;
    float loss = tsum * tsum;

    float e;
    e = beta0 * (ea[0] - 0.125f) + 0.125f; loss += e * e;
    e = beta0 * (ec[0] - 0.125f) + 0.125f; loss += e * e;
    e = beta1 * (ea[7] - 0.125f) + 0.125f; loss += e * e;
    e = beta1 * (ec[7] - 0.125f) + 0.125f; loss += e * e;

    out[b] = loss;
}

// ---------------------------------------------------------------------------
// Entry point
// ---------------------------------------------------------------------------
extern "C" void kernel_launch(void* const* d_in, const int* in_sizes, int n_in,
                              void* d_out, int out_size) {
    const float* rho_vec = (const float*)d_in[0];
    const int*   rank0   = (const int*)d_in[1];
    const int*   rank1   = (const int*)d_in[2];
    float*       out     = (float*)d_out;

    const int n = in_sizes[0] / 63;

    dim3 grid1((n + 63) / 64, 3);
    eig_kernel<<<grid1, 64>>>(rho_vec, n);

    dim3 grid2((n + 255) / 256);
    combine_kernel<<<grid2, 256>>>(rank0, rank1, out, n);
}

// round 9
// speedup vs baseline: 1.1196x; 1.1196x over previous
#include <cuda_runtime.h>
#include <cstdint>

// ============================================================================
// BESNumEigen3qubitModel — analytic restructuring + packed f32x2 Jacobi.
// 3 Hermitian 8x8 eigenproblems per batch element (rho, pt_a, pt_c);
// dm0/dm1 eigenvalues are affine maps beta*(w - 1/8) + 1/8 of rho's.
//
// R8 resubmit (infra flake): 128-thread blocks (R6 known-good config);
// 5-unconditional + guarded-extra sweep driver; branchless degenerate-pivot
// handling; guard tol 1e-9.
// ============================================================================

#define BMAX 32768

__device__ float g_eigs[3 * BMAX * 8];

using u64 = unsigned long long;

// ---------------------------------------------------------------------------
// packed f32x2 helpers
// ---------------------------------------------------------------------------
__device__ __forceinline__ u64 pk2(float lo, float hi) {
    u64 r; asm("mov.b64 %0, {%1, %2};" : "=l"(r) : "f"(lo), "f"(hi)); return r;
}
__device__ __forceinline__ void upk2(u64 v, float& lo, float& hi) {
    asm("mov.b64 {%0, %1}, %2;" : "=f"(lo), "=f"(hi) : "l"(v));
}
__device__ __forceinline__ u64 f2fma(u64 a, u64 b, u64 c) {
    u64 r; asm("fma.rn.f32x2 %0, %1, %2, %3;" : "=l"(r) : "l"(a), "l"(b), "l"(c));
    return r;
}
__device__ __forceinline__ u64 f2mul(u64 a, u64 b) {
    u64 r; asm("mul.rn.f32x2 %0, %1, %2;" : "=l"(r) : "l"(a), "l"(b));
    return r;
}
__device__ __forceinline__ u64 sw2(u64 v) {      // (lo,hi) -> (hi,lo)
    float lo, hi; upk2(v, lo, hi); return pk2(hi, lo);
}
__device__ __forceinline__ u64 cj2(u64 v) {      // conj: negate imag (hi) lane
    return v ^ 0x8000000000000000ULL;
}

// upper-triangle linear index for j<k
__host__ __device__ constexpr int uidx(int j, int k) {
    return 7 * j - (j * (j - 1)) / 2 + (k - j - 1);
}

// ---------------------------------------------------------------------------
// partial-transpose index permutations (applied at build time)
// pt_a swaps the 'a' bit (4), pt_c swaps the 'c' bit (1). Diagonal fixed.
// ---------------------------------------------------------------------------
__host__ __device__ constexpr int permR(int TYPE, int j, int k) {
    return TYPE == 0 ? j : (TYPE == 1 ? ((j & 3) | (k & 4)) : ((j & 6) | (k & 1)));
}
__host__ __device__ constexpr int permC(int TYPE, int j, int k) {
    return TYPE == 0 ? k : (TYPE == 1 ? ((k & 3) | (j & 4)) : ((k & 6) | (j & 1)));
}

// ---------------------------------------------------------------------------
// Build packed upper triangle m[28] + real diagonal d[8] of the (possibly
// partially transposed) normalized density matrix.
// v layout: [0..27] symmetric pairs, [28..55] antisymmetric, [56..62] diag.
// ---------------------------------------------------------------------------
template <int TYPE>
__device__ __forceinline__ void build8(const float* __restrict__ v,
                                       u64 m[28], float d[8]) {
    const float COEF[7] = {
        1.0f, 0.5773502691896258f, 0.4082482904638631f, 0.31622776601683794f,
        0.2581988897471611f, 0.21821789023599236f, 0.1889822365046136f
    };

    float ss = 0.f;
    float dd[8];
#pragma unroll
    for (int j = 0; j < 8; ++j) dd[j] = 0.f;

#pragma unroll
    for (int l = 1; l <= 7; ++l) {
        float x = v[55 + l];
        ss += x * x;
        x *= COEF[l - 1];
#pragma unroll
        for (int j = 0; j < 7; ++j)
            if (j < l) dd[j] += x;
        dd[l] -= (float)l * x;
    }

#pragma unroll
    for (int j = 0; j < 8; ++j) {
#pragma unroll
        for (int k = j + 1; k < 8; ++k) {
            const int p = uidx(j, k);
            float vs = v[p];
            float va = v[28 + p];
            ss += vs * vs + va * va;
            // element at permuted (R,C) is vs - i*va; mirror is conjugate
            const int R = permR(TYPE, j, k), C = permC(TYPE, j, k);
            if (R < C) m[uidx(R, C)] = pk2(vs, -va);
            else       m[uidx(C, R)] = pk2(vs,  va);
        }
    }

    float inv = rsqrtf(ss);
    u64 inv2 = pk2(inv, inv);
#pragma unroll
    for (int i = 0; i < 28; ++i) m[i] = f2mul(m[i], inv2);
#pragma unroll
    for (int j = 0; j < 8; ++j) d[j] = 0.125f + dd[j] * inv;
}

// ---------------------------------------------------------------------------
// One round-robin Jacobi sweep: 7 rounds x 4 disjoint pivot pairs.
// Angles per round computed up-front (ILP-4 MUFU chains), then 4 commuting
// rotation updates applied.
// ---------------------------------------------------------------------------
__device__ __forceinline__ void jacobi_sweep(u64 m[28], float d[8]) {
    constexpr int SCHED[7][4][2] = {
        {{0,1},{2,7},{3,6},{4,5}},
        {{0,2},{1,3},{4,7},{5,6}},
        {{0,3},{2,4},{1,5},{6,7}},
        {{0,4},{3,5},{2,6},{1,7}},
        {{0,5},{4,6},{3,7},{1,2}},
        {{0,6},{5,7},{1,4},{2,3}},
        {{0,7},{1,6},{2,5},{3,4}}
    };

#pragma unroll
    for (int r = 0; r < 7; ++r) {
        // ---- phase 1: 4 independent angle computations (ILP-4) ----
        float C[4], SR[4], SI[4];
#pragma unroll
        for (int i = 0; i < 4; ++i) {
            const int p = SCHED[r][i][0], q = SCHED[r][i][1];
            float xr, xi; upk2(m[uidx(p, q)], xr, xi);
            float r2 = xr * xr + xi * xi;
            float h = (d[q] - d[p]) * 0.5f;
            float hyp = sqrtf(h * h + r2);
            // den_safe: branchless degenerate handling. At r2=0,h=0 this
            // gives den=1e-20 -> c=1, s=0, tr=0 (identity rotation).
            float den = h + copysignf(hyp, h);
            den = copysignf(fmaxf(fabsf(den), 1e-20f), den);
            float inv_s = copysignf(rsqrtf(den * den + r2), den);
            float c   = den * inv_s;          // = |den|*rsqrt >= 0
            float scr = xr * inv_s;           // Re(s*u)
            float sci = xi * inv_s;           // Im(s*u)
            float tr  = __fdividef(r2, den);  // t*|a_pq|

            d[p] -= tr;
            d[q] += tr;
            m[uidx(p, q)] = 0ULL;
            C[i] = c; SR[i] = scr; SI[i] = sci;
        }

        // ---- phase 2: apply the 4 (commuting) rotation updates ----
#pragma unroll
        for (int i = 0; i < 4; ++i) {
            const int p = SCHED[r][i][0], q = SCHED[r][i][1];
            const float c = C[i], scr = SR[i], sci = SI[i];
            const u64 c2    = pk2(c, c);
            const u64 scr2  = pk2(scr, scr);
            const u64 mscr2 = pk2(-scr, -scr);
            const u64 spm   = pk2(-sci,  sci);   // actual-coord updates
            const u64 spc   = pk2( sci, -sci);   // conj-stored updates

            // k != p,q:
            //   np = c*kp - conj(su)*kq = c2.kp + mscr2.kq + spm.sw(kq)
            //   nq = su*kp + c*kq       = scr2.kp + spm.sw(kp) + c2.kq
            // k>q: both conj-stored -> same recurrence with spm -> spc.
            // p<k<q: p-side conj-stored -> fix with 2 XORs.
#pragma unroll
            for (int k = 0; k < 8; ++k) {
                if (k == p || k == q) continue;
                if (k < p) {
                    u64 zp = m[uidx(k, p)], zq = m[uidx(k, q)];
                    u64 np = f2fma(spm, sw2(zq), f2fma(mscr2, zq, f2mul(c2, zp)));
                    u64 nq = f2fma(spm, sw2(zp), f2fma(scr2,  zp, f2mul(c2, zq)));
                    m[uidx(k, p)] = np; m[uidx(k, q)] = nq;
                } else if (k > q) {
                    u64 zp = m[uidx(p, k)], zq = m[uidx(q, k)];
                    u64 np = f2fma(spc, sw2(zq), f2fma(mscr2, zq, f2mul(c2, zp)));
                    u64 nq = f2fma(spc, sw2(zp), f2fma(scr2,  zp, f2mul(c2, zq)));
                    m[uidx(p, k)] = np; m[uidx(q, k)] = nq;
                } else {   // p < k < q
                    u64 zp = cj2(m[uidx(p, k)]), zq = m[uidx(k, q)];
                    u64 np = f2fma(spm, sw2(zq), f2fma(mscr2, zq, f2mul(c2, zp)));
                    u64 nq = f2fma(spm, sw2(zp), f2fma(scr2,  zp, f2mul(c2, zq)));
                    m[uidx(p, k)] = cj2(np); m[uidx(k, q)] = nq;
                }
            }
        }
    }
}

// ---------------------------------------------------------------------------
// Jacobi driver: 5 unconditional sweeps, then up to 3 more gated by the
// off-diagonal norm check (warp-uniform exit). Single sweep body in binary.
// ---------------------------------------------------------------------------
__device__ __forceinline__ void jacobi8h(u64 m[28], float d[8]) {
#pragma unroll 1
    for (int sweep = 0; sweep < 8; ++sweep) {
        if (sweep >= 5) {
            u64 acc = 0ULL;
#pragma unroll
            for (int i = 0; i < 28; ++i) acc = f2fma(m[i], m[i], acc);
            float o1, o2; upk2(acc, o1, o2);
            if (__all_sync(0xFFFFFFFFu, o1 + o2 < 1e-9f)) break;
        }
        jacobi_sweep(m, d);
    }
}

// ---------------------------------------------------------------------------
// 8-element sorting network (19 comparators, ascending)
// ---------------------------------------------------------------------------
__device__ __forceinline__ void sort8(float w[8]) {
#define CAS(i, j) { float lo = fminf(w[i], w[j]); float hi = fmaxf(w[i], w[j]); w[i] = lo; w[j] = hi; }
    CAS(0,1) CAS(2,3) CAS(4,5) CAS(6,7)
    CAS(0,2) CAS(1,3) CAS(4,6) CAS(5,7)
    CAS(1,2) CAS(5,6) CAS(0,4) CAS(3,7)
    CAS(1,5) CAS(2,6)
    CAS(1,4) CAS(3,6)
    CAS(2,4) CAS(3,5)
    CAS(3,4)
#undef CAS
}

// ---------------------------------------------------------------------------
// Kernel 1: one thread per (type, batch). gridDim.y = type.
// Inputs staged through shared memory (coalesced GMEM; LDS stride 63 words
// is coprime with 32 banks -> conflict-free).
// ---------------------------------------------------------------------------
__global__ void __launch_bounds__(128)
eig_kernel(const float* __restrict__ rho_vec, int n) {
    __shared__ float sv[128 * 63];

    const int base = blockIdx.x * 128;
    const int rows = min(128, n - base);
    const int total = rows * 63;
    const float* src = rho_vec + (size_t)base * 63;
    for (int i = threadIdx.x; i < total; i += 128) sv[i] = src[i];
    __syncthreads();

    int b = base + threadIdx.x;
    const bool valid = (b < n);
    const int row = valid ? threadIdx.x : 0;   // clamp for __all_sync safety
    const int type = blockIdx.y;

    const float* v = sv + row * 63;

    u64 m[28];
    float d[8];
    if (type == 0)      build8<0>(v, m, d);
    else if (type == 1) build8<1>(v, m, d);
    else                build8<2>(v, m, d);

    jacobi8h(m, d);
    sort8(d);

    if (valid) {
        float4* dst = reinterpret_cast<float4*>(g_eigs + ((size_t)type * n + b) * 8);
        dst[0] = make_float4(d[0], d[1], d[2], d[3]);
        dst[1] = make_float4(d[4], d[5], d[6], d[7]);
    }
}

// ---------------------------------------------------------------------------
// Kernel 2: combine per-matrix eigenvalue summaries into the loss.
// ---------------------------------------------------------------------------
__global__ void __launch_bounds__(256)
combine_kernel(const int* __restrict__ rank0p, const int* __restrict__ rank1p,
               float* __restrict__ out, int n) {
    int b = blockIdx.x * blockDim.x + threadIdx.x;
    if (b >= n) return;

    const float* w  = g_eigs + (size_t)b * 8;
    const float* ea = g_eigs + ((size_t)n + b) * 8;
    const float* ec = g_eigs + ((size_t)2 * n + b) * 8;

    float wv[8];
#pragma unroll
    for (int i = 0; i < 8; ++i) wv[i] = w[i];

    const float beta0 = 1.f / (1.f - 8.f * wv[0]);
    const float beta1 = 1.f / (1.f - 8.f * wv[7]);

    const int n0 = 8 - *rank0p;
    const int n1 = 8 - *rank1p;

    float S0 = 0.f, S1 = 0.f;
#pragma unroll
    for (int i = 0; i < 8; ++i) {
        if (i < n0)       S0 += wv[i];        // n0 smallest of w
        if (i >= 8 - n1)  S1 += wv[i];        // n1 largest  of w
    }

    const float loss0 = beta0 * (S0 - 0.125f * (float)n0) + 0.125f * (float)n0;
    const float loss1 = beta1 * (S1 - 0.125f * (float)n1) + 0.125f * (float)n1;
    const float tsum = loss0 + loss1;
    float loss = tsum * tsum;

    float e;
    e = beta0 * (ea[0] - 0.125f) + 0.125f; loss += e * e;
    e = beta0 * (ec[0] - 0.125f) + 0.125f; loss += e * e;
    e = beta1 * (ea[7] - 0.125f) + 0.125f; loss += e * e;
    e = beta1 * (ec[7] - 0.125f) + 0.125f; loss += e * e;

    out[b] = loss;
}

// ---------------------------------------------------------------------------
// Entry point
// ---------------------------------------------------------------------------
extern "C" void kernel_launch(void* const* d_in, const int* in_sizes, int n_in,
                              void* d_out, int out_size) {
    const float* rho_vec = (const float*)d_in[0];
    const int*   rank0   = (const int*)d_in[1];
    const int*   rank1   = (const int*)d_in[2];
    float*       out     = (float*)d_out;

    const int n = in_sizes[0] / 63;

    dim3 grid1((n + 127) / 128, 3);
    eig_kernel<<<grid1, 128>>>(rho_vec, n);

    dim3 grid2((n + 255) / 256);
    combine_kernel<<<grid2, 256>>>(rank0, rank1, out, n);
}